// round 5
// baseline (speedup 1.0000x reference)
#include <cuda_runtime.h>
#include <cstdint>

// Covariance pooling: y[b] = (1/M) X Xᵀ - μ μᵀ, X = x[b] as [C=128, M=4096].
// Kernel 1 (partial): 128 CTAs = 64 batches x 2 K-halves; 256 threads (8 warps,
//   2 per SMSP). Warp PAIRS share a 64x64 output tile, splitting the 4 k-steps
//   of each k-tile (ks 0-1 vs 2-3) into private accumulators, combined through
//   SMEM at the end. cp.async 4-stage pipeline; raw-fp32 operands into tf32
//   mma.sync (HW truncation, debiased by CORR); exact fp32 row sums in-pipeline.
// Kernel 2 (finish): 512 CTAs combine K-halves, scale, subtract mean outer product.

#define DINLINE __device__ __forceinline__

static constexpr int Bn = 64;
static constexpr int Cn = 128;
static constexpr int Mn = 4096;
static constexpr int KHALF = Mn / 2;       // 2048
static constexpr int KT = 32;              // k floats per tile
static constexpr int NKT = KHALF / KT;     // 64 tiles
static constexpr int PAD = 36;             // floats per SMEM row
static constexpr int PADB = PAD * 4;       // 144 bytes
static constexpr int STAGES = 4;
static constexpr int STAGE_B = Cn * PADB;  // 18432 bytes
static constexpr int SMEM_B = STAGES * STAGE_B;  // 73728 (also >= 64KB combine area)

// tf32 truncation debias: 1/(1 - 2 * 2^-11 * (1/(2 ln 2)))
static constexpr float CORR = 1.00070466f;

__device__ float g_part[2 * Bn][Cn * Cn];
__device__ float g_sums[2 * Bn][Cn];

DINLINE void mma_tf32(float d[4], const uint32_t a[4], uint32_t b0, uint32_t b1) {
    asm volatile(
        "mma.sync.aligned.m16n8k8.row.col.f32.tf32.tf32.f32 "
        "{%0,%1,%2,%3}, {%4,%5,%6,%7}, {%8,%9}, {%0,%1,%2,%3};"
        : "+f"(d[0]), "+f"(d[1]), "+f"(d[2]), "+f"(d[3])
        : "r"(a[0]), "r"(a[1]), "r"(a[2]), "r"(a[3]), "r"(b0), "r"(b1));
}
DINLINE void ldsm_x4(uint32_t r[4], uint32_t addr) {
    asm volatile("ldmatrix.sync.aligned.m8n8.x4.shared.b16 {%0,%1,%2,%3}, [%4];"
                 : "=r"(r[0]), "=r"(r[1]), "=r"(r[2]), "=r"(r[3]) : "r"(addr));
}
DINLINE uint32_t smem_u32(const void* p) {
    uint32_t a;
    asm("{ .reg .u64 t; cvta.to.shared.u64 t, %1; cvt.u32.u64 %0, t; }"
        : "=r"(a) : "l"(p));
    return a;
}
DINLINE void cp16(uint32_t dst, const void* src) {
    asm volatile("cp.async.cg.shared.global [%0], [%1], 16;"
                 :: "r"(dst), "l"(src) : "memory");
}
DINLINE void cp_commit() { asm volatile("cp.async.commit_group;" ::: "memory"); }
template <int N> DINLINE void cp_wait() {
    asm volatile("cp.async.wait_group %0;" :: "n"(N) : "memory");
}

__global__ __launch_bounds__(256, 1)
void covpool_partial(const float* __restrict__ x) {
    extern __shared__ char smem[];
    const uint32_t sb = smem_u32(smem);

    const int t    = threadIdx.x;
    const int warp = t >> 5;
    const int lane = t & 31;
    const int cta  = blockIdx.x;        // 0..127
    const int s    = cta & 1;
    const int b    = cta >> 1;

    // loader: 2 threads per row, 64 B each per tile
    const int lrow  = t >> 1;
    const int lcoff = (t & 1) * 16;     // float offset: 0 or 16
    const float* xsrc = x + (size_t)b * Cn * Mn + (size_t)lrow * Mn
                          + (size_t)s * KHALF + lcoff;
    const uint32_t ldst = (uint32_t)(lrow * PADB + lcoff * 4);

    // warp pair geometry: tile index wt in 0..3 (2x2 of 64x64), k-group kg in 0..1
    const int wt = warp & 3;
    const int kg = warp >> 2;
    const int wm = (wt & 1) * 64;
    const int wn = (wt >> 1) * 64;
    const int g  = lane >> 2;
    const int tg = lane & 3;

    // ldmatrix lane offsets
    const uint32_t aoff = (uint32_t)((wm + (lane & 15)) * PADB + (lane >> 4) * 16);
    const uint32_t boff = (uint32_t)((wn + (lane & 7) + ((lane >> 4) * 8)) * PADB
                                     + ((lane >> 3) & 1) * 16);

    float acc[4][8][4];
#pragma unroll
    for (int im = 0; im < 4; im++)
#pragma unroll
        for (int in = 0; in < 8; in++)
#pragma unroll
            for (int j = 0; j < 4; j++) acc[im][in][j] = 0.0f;

    float rowsum = 0.0f;

    // prologue: stages 0..2
#pragma unroll
    for (int p = 0; p < STAGES - 1; p++) {
        const uint32_t d0 = sb + p * STAGE_B + ldst;
        const float* src = xsrc + p * KT;
#pragma unroll
        for (int i = 0; i < 4; i++) cp16(d0 + i * 16, src + i * 4);
        cp_commit();
    }

    for (int kt = 0; kt < NKT; kt++) {
        cp_wait<STAGES - 2>();
        __syncthreads();
        if (kt + STAGES - 1 < NKT) {
            const uint32_t d0 = sb + ((kt + STAGES - 1) & (STAGES - 1)) * STAGE_B + ldst;
            const float* src = xsrc + (kt + STAGES - 1) * KT;
#pragma unroll
            for (int i = 0; i < 4; i++) cp16(d0 + i * 16, src + i * 4);
        }
        cp_commit();

        const uint32_t base = sb + (kt & (STAGES - 1)) * STAGE_B;

        // row sum: this thread's half row (raw fp32, exact)
#pragma unroll
        for (int i = 0; i < 4; i++) {
            float4 v = *(const float4*)(smem + (kt & (STAGES - 1)) * STAGE_B
                                        + lrow * PADB + lcoff * 4 + i * 16);
            rowsum += v.x + v.y + v.z + v.w;
        }

        // this warp's two k-steps
#pragma unroll
        for (int ksi = 0; ksi < 2; ksi++) {
            const uint32_t k0 = (uint32_t)((kg * 2 + ksi) * 32);   // bytes
            uint32_t A[4][4], Bf[4][4];
#pragma unroll
            for (int im = 0; im < 4; im++)
                ldsm_x4(A[im], base + aoff + im * 16 * PADB + k0);
#pragma unroll
            for (int jn = 0; jn < 4; jn++)
                ldsm_x4(Bf[jn], base + boff + jn * 16 * PADB + k0);
#pragma unroll
            for (int im = 0; im < 4; im++)
#pragma unroll
                for (int jn = 0; jn < 4; jn++) {
                    mma_tf32(acc[im][2 * jn],     A[im], Bf[jn][0], Bf[jn][1]);
                    mma_tf32(acc[im][2 * jn + 1], A[im], Bf[jn][2], Bf[jn][3]);
                }
        }
    }

    // ---- combine warp-pair partials through SMEM ----
    __syncthreads();
    float* csm = (float*)smem;
    if (kg == 1) {
        float* dst = csm + ((size_t)(wt * 32 + lane)) * 128;
#pragma unroll
        for (int im = 0; im < 4; im++)
#pragma unroll
            for (int in = 0; in < 8; in++)
#pragma unroll
                for (int j = 0; j < 4; j++)
                    dst[(im * 8 + in) * 4 + j] = acc[im][in][j];
    }
    __syncthreads();
    if (kg == 0) {
        const float* srcp = csm + ((size_t)(wt * 32 + lane)) * 128;
#pragma unroll
        for (int im = 0; im < 4; im++)
#pragma unroll
            for (int in = 0; in < 8; in++)
#pragma unroll
                for (int j = 0; j < 4; j++)
                    acc[im][in][j] += srcp[(im * 8 + in) * 4 + j];

        // epilogue: partial Gram to scratch
        float* gp = g_part[cta];
#pragma unroll
        for (int im = 0; im < 4; im++) {
            const int r0 = wm + im * 16 + g;
#pragma unroll
            for (int in = 0; in < 8; in++) {
                const int c0 = wn + in * 8 + 2 * tg;
                *(float2*)(gp + (size_t)r0 * Cn + c0) =
                    make_float2(acc[im][in][0], acc[im][in][1]);
                *(float2*)(gp + (size_t)(r0 + 8) * Cn + c0) =
                    make_float2(acc[im][in][2], acc[im][in][3]);
            }
        }
    }
    // row sums: pairs of threads share a row
    rowsum += __shfl_xor_sync(0xffffffffu, rowsum, 1);
    if ((t & 1) == 0) g_sums[cta][lrow] = rowsum;
}

__global__ __launch_bounds__(256, 2)
void covpool_finish(float* __restrict__ y) {
    __shared__ float mu[Cn];
    const int t   = threadIdx.x;
    const int blk = blockIdx.x;
    const int b   = blk >> 3;
    const int q   = blk & 7;
    if (t < Cn)
        mu[t] = (g_sums[2 * b][t] + g_sums[2 * b + 1][t]) * (1.0f / (float)Mn);
    __syncthreads();

    const float4* G0 = (const float4*)g_part[2 * b];
    const float4* G1 = (const float4*)g_part[2 * b + 1];
    float4* out = (float4*)(y + (size_t)b * Cn * Cn);
    const float4* mu4 = (const float4*)mu;
    const float a = CORR * (1.0f / (float)Mn);
#pragma unroll
    for (int j = 0; j < 2; j++) {
        const int idx = q * 512 + t + j * 256;    // float4 index in [0,4096)
        const int r   = idx >> 5;
        const float mr = mu[r];
        const float4 m = mu4[idx & 31];
        const float4 p = G0[idx];
        const float4 c = G1[idx];
        float4 o;
        o.x = (p.x + c.x) * a - mr * m.x;
        o.y = (p.y + c.y) * a - mr * m.y;
        o.z = (p.z + c.z) * a - mr * m.z;
        o.w = (p.w + c.w) * a - mr * m.w;
        out[idx] = o;
    }
}

extern "C" void kernel_launch(void* const* d_in, const int* in_sizes, int n_in,
                              void* d_out, int out_size) {
    (void)in_sizes; (void)n_in; (void)out_size;
    const float* x = (const float*)d_in[0];
    float* y = (float*)d_out;
    cudaFuncSetAttribute(covpool_partial,
                         cudaFuncAttributeMaxDynamicSharedMemorySize, SMEM_B);
    covpool_partial<<<2 * Bn, 256, SMEM_B>>>(x);
    covpool_finish<<<8 * Bn, 256>>>(y);
}